// round 14
// baseline (speedup 1.0000x reference)
#include <cuda_runtime.h>

// Warp1DOp: smem row staging with occupancy (fixes R6's occ=1 serialization).
// Block = (n, h, 8-channel slab); 256 threads; grid = N*H*4 = 6144.
//   Stage: 8 padded channel rows via coalesced LDG.128/STS.128 (10 float4/thread)
//          + per-pixel coords (dx, i0) into smem. ONE __syncthreads.
//   Gather: warp wi owns channel wi; lane handles px = lane + 32k (40 iters);
//          two scalar LDS taps (randomized banks), coalesced STG.32.
// ~50 KB smem -> 4 CTAs/SM, so staging DRAM streams overlap gather crossbar
// work across CTAs. All GLOBAL traffic is unit-stride.
//
// Padded row: row[4+j] = img[j], row[3] = row[1284] = 0 (zeros padding).
// i0 = floor(clip(w - disp, -1, W) + 1) + 3 in [3,1284]; i1 = i0 + (dx>0).

#define N_ 4
#define C_ 32
#define H_ 384
#define W_ 1280
#define HW_ (H_ * W_)
#define CHW_ (C_ * HW_)
#define NH_ (N_ * H_)

#define CB_ 8                          // channels per block
#define NBLK_ (NH_ * (C_ / CB_))       // 6144
#define RSTRIDE 1288
#define ROWS_FLOATS (CB_ * RSTRIDE)    // 10304 floats
#define SMEM_BYTES (ROWS_FLOATS * 4 + W_ * 8)   // 41216 + 10240 = 51456 B

__global__ __launch_bounds__(256) void warp1d_kernel(
    const float* __restrict__ img,
    const float* __restrict__ disp,
    float* __restrict__ out)
{
    extern __shared__ float smem[];
    float*  rows   = smem;                                    // [CB_][RSTRIDE]
    float2* coords = reinterpret_cast<float2*>(smem + ROWS_FLOATS);  // [W_]

    const int tid  = threadIdx.x;
    const int bid  = blockIdx.x;
    const int nh   = bid >> 2;            // n*H + h
    const int cblk = (bid & 3) * CB_;     // first channel of this slab

    const size_t base  = (size_t)(nh / H_) * CHW_ + (size_t)(nh % H_) * W_;
    const size_t cbase = base + (size_t)cblk * HW_;

    // zero pads (one thread per staged channel)
    if (tid < CB_) {
        rows[tid * RSTRIDE + 3]    = 0.0f;
        rows[tid * RSTRIDE + 1284] = 0.0f;
    }

    // ---- stage 8 channel rows: 10 float4 per thread, fully coalesced ----
#pragma unroll
    for (int it = 0; it < 10; ++it) {
        int idx4 = tid + it * 256;                  // over CB_*W_/4 = 2560
        int c    = idx4 / (W_ / 4);
        int w4   = idx4 - c * (W_ / 4);
        float4 v = *reinterpret_cast<const float4*>(img + cbase + (size_t)c * HW_ + w4 * 4);
        *reinterpret_cast<float4*>(&rows[c * RSTRIDE + 4 + w4 * 4]) = v;
    }

    // ---- coords: once per pixel ----
    const float* __restrict__ drow = disp + (size_t)nh * W_;
#pragma unroll
    for (int px = tid; px < W_; px += 256) {
        float d = __ldg(drow + px);
        float x = (float)px - d;
        x = fminf(fmaxf(x, -1.0f), (float)W_) + 1.0f;   // [0, W+1]
        float xf = floorf(x);
        float dx = x - xf;
        int   i0 = (int)xf + 3;
        coords[px] = make_float2(dx, __int_as_float(i0));
    }

    __syncthreads();

    // ---- gather: warp wi owns channel wi; lane owns px = lane + 32k ----
    const int wi   = tid >> 5;
    const int lane = tid & 31;
    const float* __restrict__ rowc = rows + wi * RSTRIDE;
    float* __restrict__ orow = out + cbase + (size_t)wi * HW_;

#pragma unroll 8
    for (int k = 0; k < W_ / 32; ++k) {
        int px = lane + 32 * k;
        float2 cd = coords[px];               // conflict-free LDS.64
        float dx  = cd.x;
        int   i0  = __float_as_int(cd.y);
        int   i1  = i0 + (dx > 0.0f ? 1 : 0);
        float a = rowc[i0];
        float b = rowc[i1];
        orow[px] = (1.0f - dx) * a + dx * b;  // coalesced STG.32
    }
}

extern "C" void kernel_launch(void* const* d_in, const int* in_sizes, int n_in,
                              void* d_out, int out_size)
{
    const float* img  = (const float*)d_in[0];
    const float* disp = (const float*)d_in[1];
    float* out = (float*)d_out;

    cudaFuncSetAttribute(warp1d_kernel,
                         cudaFuncAttributeMaxDynamicSharedMemorySize, SMEM_BYTES);
    warp1d_kernel<<<NBLK_, 256, SMEM_BYTES>>>(img, disp, out);
}